// round 12
// baseline (speedup 1.0000x reference)
#include <cuda_runtime.h>
#include <cuda_fp16.h>
#include <math.h>
#include <stdint.h>

#define B_    4
#define T_    1024
#define C_    2048
#define H_    32
#define KV_   8
#define D_    64
#define M_TOK 4096
#define KVDIM 512
#define NQKV  3072          // 2048 q + 512 k + 512 v
#define NALL  5120          // NQKV + C_ (wp)

// ---------------- scratch (device globals; no allocation allowed) ----------
__device__ __half g_qh[M_TOK * C_];         // fp16 q post-rope (scaled)
__device__ __half g_kh[M_TOK * KVDIM];      // fp16 k post-rope
__device__ __half g_vp[M_TOK * KVDIM];      // fp16 v, [tok/2][dk][2] packed
__device__ __half g_xh[M_TOK * C_];         // fp16(x)        [m][k]
__device__ __half g_wqkvT[NQKV * C_];       // fp16 weights   [n][k]
__device__ __half g_wpT[C_ * C_];           // fp16(Wp)       [n][k]
__device__ __half g_atth[M_TOK * C_];       // fp16 attention out
__device__ float2 g_rope[T_ * 32];          // cos/sin table [t][pair]

// ------------------------- helpers -----------------------------------------
__device__ __forceinline__ float ex2f(float x) {
    float r;
    asm("ex2.approx.f32 %0, %1;" : "=f"(r) : "f"(x));
    return r;
}
__device__ __forceinline__ uint32_t packh2(float a, float b) {
    __half2 h = __floats2half2_rn(a, b);
    return *(uint32_t*)&h;
}
__device__ __forceinline__ void mma_f16(float c[4], const uint32_t a[4],
                                        const uint32_t b[2]) {
    asm volatile(
        "mma.sync.aligned.m16n8k16.row.col.f32.f16.f16.f32 "
        "{%0,%1,%2,%3}, {%4,%5,%6,%7}, {%8,%9}, {%0,%1,%2,%3};"
        : "+f"(c[0]), "+f"(c[1]), "+f"(c[2]), "+f"(c[3])
        : "r"(a[0]), "r"(a[1]), "r"(a[2]), "r"(a[3]), "r"(b[0]), "r"(b[1]));
}
__device__ __forceinline__ void ldsm4(uint32_t& r0, uint32_t& r1,
                                      uint32_t& r2, uint32_t& r3,
                                      uint32_t addr) {
    asm volatile(
        "ldmatrix.sync.aligned.m8n8.x4.shared.b16 {%0,%1,%2,%3}, [%4];"
        : "=r"(r0), "=r"(r1), "=r"(r2), "=r"(r3) : "r"(addr));
}
__device__ __forceinline__ uint32_t smem_u32(const void* p) {
    uint32_t a;
    asm("{ .reg .u64 t; cvta.to.shared.u64 t, %1; cvt.u32.u64 %0, t; }"
        : "=r"(a) : "l"(p));
    return a;
}
__device__ __forceinline__ void cpa16(uint32_t dst, const void* src) {
    asm volatile("cp.async.cg.shared.global [%0], [%1], 16;"
                 :: "r"(dst), "l"(src) : "memory");
}
__device__ __forceinline__ void cpa_commit() {
    asm volatile("cp.async.commit_group;" ::: "memory");
}
template <int N> __device__ __forceinline__ void cpa_wait() {
    asm volatile("cp.async.wait_group %0;" :: "n"(N) : "memory");
}

// ---------------- x -> fp16, rope table ------------------------------------
__global__ void cvt_x(const float* __restrict__ x) {
    int i4 = blockIdx.x * blockDim.x + threadIdx.x;
    if (i4 < T_ * 32) {
        int t = i4 >> 5, p = i4 & 31;
        float inv = powf(10000.0f, -(float)p / 32.0f);
        float s, c;
        sincosf((float)t * inv, &s, &c);
        g_rope[i4] = make_float2(c, s);
    }
    if (i4 < M_TOK * C_ / 4) {
        float4 v = ((const float4*)x)[i4];
        __half2* dst = (__half2*)(g_xh) + i4 * 2;
        dst[0] = __floats2half2_rn(v.x, v.y);
        dst[1] = __floats2half2_rn(v.z, v.w);
    }
}

// ---------------- weight transpose: fp32 [k][n] -> fp16 [n][k] -------------
// Logical combined n axis: [0,2048)=Wq, [2048,2560)=Wk, [2560,3072)=Wv,
// [3072,5120)=Wp. All region boundaries are 64-aligned, so a 64-wide n tile
// never straddles regions.
__global__ void __launch_bounds__(256) wtrans(const float* __restrict__ Wq,
                                              const float* __restrict__ Wk,
                                              const float* __restrict__ Wv,
                                              const float* __restrict__ Wp) {
    __shared__ float ts[64][65];
    const int tid = threadIdx.x;
    const int n0 = blockIdx.x * 64;
    const int k0 = blockIdx.y * 64;

    const float* src;
    int ldn, noff;
    if (n0 < 2048)      { src = Wq; ldn = 2048; noff = 0; }
    else if (n0 < 2560) { src = Wk; ldn = 512;  noff = 2048; }
    else if (n0 < 3072) { src = Wv; ldn = 512;  noff = 2560; }
    else                { src = Wp; ldn = 2048; noff = 3072; }

    // read 64x64 fp32 tile, coalesced along n
#pragma unroll
    for (int p = 0; p < 4; ++p) {
        int kr = p * 16 + (tid >> 4);
        int nc = (tid & 15) * 4;
        float4 v = *(const float4*)(src + (size_t)(k0 + kr) * ldn +
                                    (n0 - noff) + nc);
        ts[kr][nc] = v.x; ts[kr][nc + 1] = v.y;
        ts[kr][nc + 2] = v.z; ts[kr][nc + 3] = v.w;
    }
    __syncthreads();

    // write fp16 [n][k], coalesced along k (32B per thread)
    __half* outp = (n0 < 3072) ? g_wqkvT + (size_t)n0 * C_
                               : g_wpT + (size_t)(n0 - 3072) * C_;
    int nr = tid >> 2;
    int kc = (tid & 3) * 16;
    __half2 h[8];
#pragma unroll
    for (int j = 0; j < 8; ++j)
        h[j] = __floats2half2_rn(ts[kc + 2 * j][nr], ts[kc + 2 * j + 1][nr]);
    *(uint4*)(outp + (size_t)nr * C_ + k0 + kc)     = *(uint4*)&h[0];
    *(uint4*)(outp + (size_t)nr * C_ + k0 + kc + 8) = *(uint4*)&h[4];
}

// ============ fp16 cp.async 2-stage GEMM, K-slab 64, 2 CTAs/SM =============
// 128x128x64 slab, 8 warps (2x4), warp tile 64x32, m16n8k16, f32 accum.
// A [m][k] and B [n][k] both k-major; ALL fragments via ldmatrix.x4.
#define AW 36     // 32 data + 4 pad (half2 words per row)
#define A_WORDS (128 * AW)       // 4608 words per (A or B) tile
#define STG_W (2 * A_WORDS)      // 9216
#define SMEM_G (2 * STG_W * 4)   // 73728 B -> 2 CTAs/SM
#define CW 68     // V repack staging

template <int SPLIT>
__global__ void __launch_bounds__(256, 2)
gemm_hp(const __half* __restrict__ A, const __half* __restrict__ Bm,
        float* __restrict__ C0, int M, int N, int K) {
    extern __shared__ uint32_t sm[];

    const int tid  = threadIdx.x;
    const int bm   = blockIdx.y * 128;
    const int bn   = blockIdx.x * 128;
    const int warp = tid >> 5;
    const int lane = tid & 31;
    const int g    = lane >> 2;
    const int tg   = lane & 3;
    const int wm   = (warp >> 2) * 64;
    const int wn   = (warp & 3) * 32;
    const int nslab = K >> 6;

    const uint32_t sbase = smem_u32(sm);
    // A ldmatrix base: row wm+(lane&15), col-half (lane>>4)*16B
    const uint32_t lds_a = ((wm + (lane & 15)) * AW + ((lane >> 4) << 2)) * 4;
    // B ldmatrix base: tile lane>>3 (nt), row lane&7
    const uint32_t lds_b = ((wn + ((lane >> 3) << 3) + (lane & 7)) * AW) * 4;

    float acc[4][4][4];
#pragma unroll
    for (int i = 0; i < 4; ++i)
#pragma unroll
        for (int j = 0; j < 4; ++j)
#pragma unroll
            for (int c = 0; c < 4; ++c) acc[i][j][c] = 0.0f;

#define ISSUE_STAGE(s, kb)                                                  \
    do {                                                                    \
        uint32_t ab = sbase + (s) * (STG_W * 4);                            \
        uint32_t bb = ab + A_WORDS * 4;                                     \
        _Pragma("unroll")                                                   \
        for (int l = 0; l < 4; ++l) {                                       \
            int id = l * 256 + tid;                                         \
            int row = id >> 3, wo = (id & 7) * 4;                           \
            cpa16(ab + (uint32_t)(row * AW + wo) * 4,                       \
                  A + (size_t)(bm + row) * K + (kb) + wo * 2);              \
        }                                                                   \
        _Pragma("unroll")                                                   \
        for (int l = 0; l < 4; ++l) {                                       \
            int id = l * 256 + tid;                                         \
            int row = id >> 3, wo = (id & 7) * 4;                           \
            cpa16(bb + (uint32_t)(row * AW + wo) * 4,                       \
                  Bm + (size_t)(bn + row) * K + (kb) + wo * 2);             \
        }                                                                   \
    } while (0)

    ISSUE_STAGE(0, 0);
    cpa_commit();

    for (int i = 0; i < nslab; ++i) {
        if (i + 1 < nslab) {
            ISSUE_STAGE((i + 1) & 1, (i + 1) << 6);
            cpa_commit();
            cpa_wait<1>();
        } else {
            cpa_wait<0>();
        }
        __syncthreads();

        const uint32_t stg = sbase + (i & 1) * (STG_W * 4);
        const uint32_t a_sm = stg + lds_a;
        const uint32_t b_sm = stg + A_WORDS * 4 + lds_b;

#pragma unroll
        for (int ks = 0; ks < 4; ++ks) {        // four k16 chunks
            const int kp = ks * 8;
            uint32_t af[4][4], bf[4][2];
#pragma unroll
            for (int mt = 0; mt < 4; ++mt)
                ldsm4(af[mt][0], af[mt][1], af[mt][2], af[mt][3],
                      a_sm + (uint32_t)(mt * 16 * AW + kp) * 4);
            ldsm4(bf[0][0], bf[1][0], bf[2][0], bf[3][0],
                  b_sm + (uint32_t)kp * 4);
            ldsm4(bf[0][1], bf[1][1], bf[2][1], bf[3][1],
                  b_sm + (uint32_t)kp * 4 + 16);
#pragma unroll
            for (int mt = 0; mt < 4; ++mt)
#pragma unroll
                for (int nt = 0; nt < 4; ++nt)
                    mma_f16(acc[mt][nt], af[mt], bf[nt]);
        }
        __syncthreads();
    }

    if (SPLIT && bn >= 2560) {
        // ---- V tile: repack through smem into [tok/2][dk][2] fp16 ----
#pragma unroll
        for (int mt = 0; mt < 4; ++mt)
#pragma unroll
            for (int nt = 0; nt < 4; ++nt) {
                int r0 = wm + mt * 16 + g;
                int cw = (wn + nt * 8 + tg * 2) >> 1;
                sm[r0 * CW + cw]       = packh2(acc[mt][nt][0], acc[mt][nt][1]);
                sm[(r0 + 8) * CW + cw] = packh2(acc[mt][nt][2], acc[mt][nt][3]);
            }
        __syncthreads();
        uint32_t* vp32 = (uint32_t*)g_vp;
#pragma unroll
        for (int it = 0; it < 16; ++it) {
            int id = it * 256 + tid;
            int tp = id >> 6, cw = id & 63;
            uint32_t a = sm[(2 * tp) * CW + cw];
            uint32_t b = sm[(2 * tp + 1) * CW + cw];
            __half2 ah = *(__half2*)&a, bh = *(__half2*)&b;
            uint2 o;
            o.x = packh2(__low2float(ah),  __low2float(bh));
            o.y = packh2(__high2float(ah), __high2float(bh));
            *(uint2*)(vp32 + ((size_t)(bm >> 1) + tp) * 512 +
                      (bn - 2560) + 2 * cw) = o;
        }
        return;
    }

    if (SPLIT) {
        // ---- q/k tile: fused RoPE, write fp16 (q scaled for softmax) ----
        const float SCq = 0.125f * 1.4426950408889634f;
        const bool isq = (bn < 2048);
        const float scale = isq ? SCq : 1.0f;
        __half* dst = isq ? g_qh : g_kh;
        const int ldc = isq ? 2048 : 512;
        const int coff = isq ? bn : bn - 2048;
#pragma unroll
        for (int mt = 0; mt < 4; ++mt) {
#pragma unroll
            for (int nt = 0; nt < 4; ++nt) {
                int col = coff + wn + nt * 8 + tg * 2;
                int p = (col & 63) >> 1;
                int r0 = bm + wm + mt * 16 + g;
                float2 cs0 = g_rope[(r0 & (T_ - 1)) * 32 + p];
                float2 cs1 = g_rope[((r0 + 8) & (T_ - 1)) * 32 + p];
                float a0 = acc[mt][nt][0], a1 = acc[mt][nt][1];
                float a2 = acc[mt][nt][2], a3 = acc[mt][nt][3];
                *(__half2*)(dst + (size_t)r0 * ldc + col) =
                    __floats2half2_rn((a0 * cs0.x - a1 * cs0.y) * scale,
                                      (a1 * cs0.x + a0 * cs0.y) * scale);
                *(__half2*)(dst + (size_t)(r0 + 8) * ldc + col) =
                    __floats2half2_rn((a2 * cs1.x - a3 * cs1.y) * scale,
                                      (a3 * cs1.x + a2 * cs1.y) * scale);
            }
        }
        return;
    }

    // ---- plain fp32 output (out-proj) ----
#pragma unroll
    for (int mt = 0; mt < 4; ++mt) {
#pragma unroll
        for (int nt = 0; nt < 4; ++nt) {
            int r0  = bm + wm + mt * 16 + g;
            int col = bn + wn + nt * 8 + tg * 2;
            *(float2*)(C0 + (size_t)r0 * N + col) =
                make_float2(acc[mt][nt][0], acc[mt][nt][1]);
            *(float2*)(C0 + (size_t)(r0 + 8) * N + col) =
                make_float2(acc[mt][nt][2], acc[mt][nt][3]);
        }
    }
}

// ---------------- fp16 flash attention (FA2 fragment identity) -------------
#define KW2 36
#define VW2 68
#define KSTG (64 * KW2)
#define VSTG (32 * VW2)
#define SMEM_F ((2 * KSTG + 2 * VSTG) * 4)

__global__ void __launch_bounds__(128, 3)
flash_tc(const __half* __restrict__ Q, const __half* __restrict__ K,
         const __half* __restrict__ Vp, __half* __restrict__ O) {
    extern __shared__ uint32_t fsm[];
    const uint32_t sbase = smem_u32(fsm);

    const int tid  = threadIdx.x;
    const int warp = tid >> 5;
    const int lane = tid & 31;
    const int g    = lane >> 2;
    const int tg   = lane & 3;

    const int qi = blockIdx.x;
    const int bh = blockIdx.y;
    const int b  = bh >> 5;
    const int h  = bh & 31;
    const int hk = h >> 2;
    const int q0 = qi * 64;
    const int qrow = warp * 16;
    const int bT = b * T_;

#define ISSUE_KV(j, s)                                                      \
    do {                                                                    \
        uint32_t kb = sbase + (s) * (KSTG * 4);                             \
        uint32_t vb = sbase + (2 * KSTG + (s) * VSTG) * 4;                  \
        int k0i = (j) * 64;                                                 \
        _Pragma("unroll")                                                   \
        for (int l = 0; l < 4; ++l) {                                       \
            int id = l * 128 + tid;                                         \
            int r = id >> 3, c8 = id & 7;                                   \
            cpa16(kb + (uint32_t)(r * KW2 + c8 * 4) * 4,                    \
                  K + (size_t)(bT + k0i + r) * KVDIM + hk * D_ + c8 * 8);   \
        }                                                                   \
        _Pragma("unroll")                                                   \
        for (int l = 0; l < 4; ++l) {                                       \
            int id = l * 128 + tid;                                         \
            int t2 = id >> 4, c16 = id & 15;                                \
            cpa16(vb + (uint32_t)(t2 * VW2 + c16 * 4) * 4,                  \
                  Vp + ((size_t)((bT + k0i) >> 1) + t2) * (2 * KVDIM) +     \
                      hk * 128 + c16 * 8);                                  \
        }                                                                   \
    } while (0)

    {
        uint32_t qb = sbase + KSTG * 4;
#pragma unroll
        for (int l = 0; l < 4; ++l) {
            int id = l * 128 + tid;
            int r = id >> 3, c8 = id & 7;
            cpa16(qb + (uint32_t)(r * KW2 + c8 * 4) * 4,
                  Q + (size_t)(bT + q0 + r) * C_ + h * D_ + c8 * 8);
        }
        cpa_commit();
    }
    ISSUE_KV(0, 0);
    cpa_commit();

    cpa_wait<1>();
    __syncthreads();

    uint32_t qf[4][4];
    {
        const uint32_t* Qs = fsm + KSTG;
#pragma unroll
        for (int c = 0; c < 4; ++c) {
            qf[c][0] = Qs[(qrow + g)     * KW2 + 8 * c + tg];
            qf[c][1] = Qs[(qrow + g + 8) * KW2 + 8 * c + tg];
            qf[c][2] = Qs[(qrow + g)     * KW2 + 8 * c + tg + 4];
            qf[c][3] = Qs[(qrow + g + 8) * KW2 + 8 * c + tg + 4];
        }
    }
    __syncthreads();

    if (qi >= 1) {
        ISSUE_KV(1, 1);
        cpa_commit();
    }

    float m1 = -INFINITY, m2 = -INFINITY, l1 = 0.0f, l2 = 0.0f;
    float oacc[8][4];
#pragma unroll
    for (int nt = 0; nt < 8; ++nt)
#pragma unroll
        for (int c = 0; c < 4; ++c) oacc[nt][c] = 0.0f;

    for (int j = 0; j <= qi; ++j) {
        if (j < qi) cpa_wait<1>(); else cpa_wait<0>();
        __syncthreads();

        const uint32_t* Ks = fsm + (j & 1) * KSTG;
        const uint32_t* Vs = fsm + 2 * KSTG + (j & 1) * VSTG;
        const int k0 = j * 64;

        float sacc[8][4];
#pragma unroll
        for (int nt = 0; nt < 8; ++nt)
#pragma unroll
            for (int c = 0; c < 4; ++c) sacc[nt][c] = 0.0f;

#pragma unroll
        for (int nt = 0; nt < 8; ++nt) {
#pragma unroll
            for (int c = 0; c < 4; ++c) {
                uint32_t bf[2];
                bf[0] = Ks[(nt * 8 + g) * KW2 + 8 * c + tg];
                bf[1] = Ks[(nt * 8 + g) * KW2 + 8 * c + tg + 4];
                mma_f16(sacc[nt], qf[c], bf);
            }
        }

        if (j == qi) {
            int r1 = q0 + qrow + g, r2 = r1 + 8;
#pragma unroll
            for (int nt = 0; nt < 8; ++nt) {
                int c0 = k0 + nt * 8 + tg * 2;
                if (c0     > r1) sacc[nt][0] = -INFINITY;
                if (c0 + 1 > r1) sacc[nt][1] = -INFINITY;
                if (c0     > r2) sacc[nt][2] = -INFINITY;
                if (c0 + 1 > r2) sacc[nt][3] = -INFINITY;
            }
        }

        float a1 = -INFINITY, a2 = -INFINITY;
#pragma unroll
        for (int nt = 0; nt < 8; ++nt) {
            a1 = fmaxf(a1, fmaxf(sacc[nt][0], sacc[nt][1]));
            a2 = fmaxf(a2, fmaxf(sacc[nt][2], sacc[nt][3]));
        }
        a1 = fmaxf(a1, __shfl_xor_sync(0xffffffff, a1, 1));
        a1 = fmaxf(a1, __shfl_xor_sync(0xffffffff, a1, 2));
        a2 = fmaxf(a2, __shfl_xor_sync(0xffffffff, a2, 1));
        a2 = fmaxf(a2, __shfl_xor_sync(0xffffffff, a2, 2));

        float mn1 = fmaxf(m1, a1), mn2 = fmaxf(m2, a2);
        float al1 = ex2f(m1 - mn1), al2 = ex2f(m2 - mn2);

        float s1 = 0.0f, s2 = 0.0f;
#pragma unroll
        for (int nt = 0; nt < 8; ++nt) {
            sacc[nt][0] = ex2f(sacc[nt][0] - mn1);
            sacc[nt][1] = ex2f(sacc[nt][1] - mn1);
            sacc[nt][2] = ex2f(sacc[nt][2] - mn2);
            sacc[nt][3] = ex2f(sacc[nt][3] - mn2);
            s1 += sacc[nt][0] + sacc[nt][1];
            s2 += sacc[nt][2] + sacc[nt][3];
        }
        s1 += __shfl_xor_sync(0xffffffff, s1, 1);
        s1 += __shfl_xor_sync(0xffffffff, s1, 2);
        s2 += __shfl_xor_sync(0xffffffff, s2, 1);
        s2 += __shfl_xor_sync(0xffffffff, s2, 2);

        l1 = l1 * al1 + s1;
        l2 = l2 * al2 + s2;
        m1 = mn1;
        m2 = mn2;

#pragma unroll
        for (int nt = 0; nt < 8; ++nt) {
            oacc[nt][0] *= al1; oacc[nt][1] *= al1;
            oacc[nt][2] *= al2; oacc[nt][3] *= al2;
        }

#pragma unroll
        for (int c = 0; c < 4; ++c) {
            uint32_t af[4];
            af[0] = packh2(sacc[2 * c][0],     sacc[2 * c][1]);
            af[1] = packh2(sacc[2 * c][2],     sacc[2 * c][3]);
            af[2] = packh2(sacc[2 * c + 1][0], sacc[2 * c + 1][1]);
            af[3] = packh2(sacc[2 * c + 1][2], sacc[2 * c + 1][3]);
#pragma unroll
            for (int nt = 0; nt < 8; ++nt) {
                uint32_t bf[2];
                bf[0] = Vs[(8 * c + tg)     * VW2 + nt * 8 + g];
                bf[1] = Vs[(8 * c + tg + 4) * VW2 + nt * 8 + g];
                mma_f16(oacc[nt], af, bf);
            }
        }

        __syncthreads();
        if (j + 2 <= qi) {
            ISSUE_KV(j + 2, j & 1);
            cpa_commit();
        }
    }

    float i1 = 1.0f / l1, i2 = 1.0f / l2;
    int r1 = q0 + qrow + g, r2 = r1 + 8;
#pragma unroll
    for (int nt = 0; nt < 8; ++nt) {
        int col = h * D_ + nt * 8 + tg * 2;
        __half2 lo = __floats2half2_rn(oacc[nt][0] * i1, oacc[nt][1] * i1);
        __half2 hi = __floats2half2_rn(oacc[nt][2] * i2, oacc[nt][3] * i2);
        *(__half2*)(O + (size_t)(bT + r1) * C_ + col) = lo;
        *(__half2*)(O + (size_t)(bT + r2) * C_ + col) = hi;
    }
}

// ---------------------------------------------------------------------------
extern "C" void kernel_launch(void* const* d_in, const int* in_sizes, int n_in,
                              void* d_out, int out_size) {
    const float* x  = (const float*)d_in[0];
    const float* Wq = (const float*)d_in[1];
    const float* Wk = (const float*)d_in[2];
    const float* Wv = (const float*)d_in[3];
    const float* Wp = (const float*)d_in[4];
    float* out = (float*)d_out;

    __half *qh, *kh, *vp, *xh, *wqkvT, *wpT, *atth;
    cudaGetSymbolAddress((void**)&qh,    g_qh);
    cudaGetSymbolAddress((void**)&kh,    g_kh);
    cudaGetSymbolAddress((void**)&vp,    g_vp);
    cudaGetSymbolAddress((void**)&xh,    g_xh);
    cudaGetSymbolAddress((void**)&wqkvT, g_wqkvT);
    cudaGetSymbolAddress((void**)&wpT,   g_wpT);
    cudaGetSymbolAddress((void**)&atth,  g_atth);

    cudaFuncSetAttribute(gemm_hp<1>,
                         cudaFuncAttributeMaxDynamicSharedMemorySize, SMEM_G);
    cudaFuncSetAttribute(gemm_hp<0>,
                         cudaFuncAttributeMaxDynamicSharedMemorySize, SMEM_G);
    cudaFuncSetAttribute(flash_tc,
                         cudaFuncAttributeMaxDynamicSharedMemorySize, SMEM_F);

    // 1a. x -> fp16 + rope table
    cvt_x<<<(M_TOK * C_ / 4 + 255) / 256, 256>>>(x);
    // 1b. weights -> fp16 [n][k] (transposed)
    wtrans<<<dim3(NALL / 64, C_ / 64), 256>>>(Wq, Wk, Wv, Wp);

    // 2. fused QKV projection + RoPE epilogue (q/k fp16 rotated, v packed)
    gemm_hp<1><<<dim3(NQKV / 128, M_TOK / 128), 256, SMEM_G>>>(
        xh, wqkvT, nullptr, M_TOK, NQKV, C_);

    // 3. causal flash attention with GQA (fp16 mma)
    flash_tc<<<dim3(T_ / 64, B_ * H_), 128, SMEM_F>>>(qh, kh, vp, atth);

    // 4. output projection (fp16 mma)
    gemm_hp<0><<<dim3(C_ / 128, M_TOK / 128), 256, SMEM_G>>>(
        atth, wpT, out, M_TOK, C_, C_);
}

// round 13
// speedup vs baseline: 1.1231x; 1.1231x over previous
#include <cuda_runtime.h>
#include <cuda_fp16.h>
#include <math.h>
#include <stdint.h>

#define B_    4
#define T_    1024
#define C_    2048
#define H_    32
#define KV_   8
#define D_    64
#define M_TOK 4096
#define KVDIM 512
#define NQKV  3072          // 2048 q + 512 k + 512 v

// ---------------- scratch (device globals; no allocation allowed) ----------
__device__ __half g_qh[M_TOK * C_];         // fp16 q post-rope (scaled)
__device__ __half g_kh[M_TOK * KVDIM];      // fp16 k post-rope
__device__ __half g_vp[M_TOK * KVDIM];      // fp16 v, [tok/2][dk][2] packed
__device__ __half g_xh[M_TOK * C_];         // fp16(x)       [m][k]
__device__ __half g_wqkvh[C_ * NQKV];       // fp16 weights  [k/2][n][2]
__device__ __half g_wph[C_ * C_];           // fp16(Wp)      [k/2][n][2]
__device__ __half g_atth[M_TOK * C_];       // fp16 attention out
__device__ float2 g_rope[T_ * 32];          // cos/sin table [t][pair]

// ------------------------- helpers -----------------------------------------
__device__ __forceinline__ float ex2f(float x) {
    float r;
    asm("ex2.approx.f32 %0, %1;" : "=f"(r) : "f"(x));
    return r;
}
__device__ __forceinline__ uint32_t packh2(float a, float b) {
    __half2 h = __floats2half2_rn(a, b);
    return *(uint32_t*)&h;
}
__device__ __forceinline__ void mma_f16(float c[4], const uint32_t a[4],
                                        const uint32_t b[2]) {
    asm volatile(
        "mma.sync.aligned.m16n8k16.row.col.f32.f16.f16.f32 "
        "{%0,%1,%2,%3}, {%4,%5,%6,%7}, {%8,%9}, {%0,%1,%2,%3};"
        : "+f"(c[0]), "+f"(c[1]), "+f"(c[2]), "+f"(c[3])
        : "r"(a[0]), "r"(a[1]), "r"(a[2]), "r"(a[3]), "r"(b[0]), "r"(b[1]));
}
__device__ __forceinline__ void ldsm4(uint32_t& r0, uint32_t& r1,
                                      uint32_t& r2, uint32_t& r3,
                                      uint32_t addr) {
    asm volatile(
        "ldmatrix.sync.aligned.m8n8.x4.shared.b16 {%0,%1,%2,%3}, [%4];"
        : "=r"(r0), "=r"(r1), "=r"(r2), "=r"(r3) : "r"(addr));
}
__device__ __forceinline__ uint32_t smem_u32(const void* p) {
    uint32_t a;
    asm("{ .reg .u64 t; cvta.to.shared.u64 t, %1; cvt.u32.u64 %0, t; }"
        : "=r"(a) : "l"(p));
    return a;
}
__device__ __forceinline__ void cpa16(uint32_t dst, const void* src) {
    asm volatile("cp.async.cg.shared.global [%0], [%1], 16;"
                 :: "r"(dst), "l"(src) : "memory");
}
__device__ __forceinline__ void cpa_commit() {
    asm volatile("cp.async.commit_group;" ::: "memory");
}
template <int N> __device__ __forceinline__ void cpa_wait() {
    asm volatile("cp.async.wait_group %0;" :: "n"(N) : "memory");
}

// ---------------- fp16 pre-conversion / weight interleave / rope table -----
__global__ void cvt_pack(const float* __restrict__ x,
                         const float* __restrict__ Wq,
                         const float* __restrict__ Wk,
                         const float* __restrict__ Wv,
                         const float* __restrict__ Wp) {
    int i4 = blockIdx.x * blockDim.x + threadIdx.x;

    if (i4 < T_ * 32) {
        int t = i4 >> 5, p = i4 & 31;
        float inv = powf(10000.0f, -(float)p / 32.0f);
        float s, c;
        sincosf((float)t * inv, &s, &c);
        g_rope[i4] = make_float2(c, s);
    }
    if (i4 < M_TOK * C_ / 4) {
        float4 v = ((const float4*)x)[i4];
        __half2* dst = (__half2*)(g_xh) + i4 * 2;
        dst[0] = __floats2half2_rn(v.x, v.y);
        dst[1] = __floats2half2_rn(v.z, v.w);
    }
    if (i4 < (C_ / 2) * (NQKV / 4)) {
        int r = i4 / (NQKV / 4);
        int n = (i4 % (NQKV / 4)) * 4;
        int k0 = 2 * r;
        const float *s0, *s1;
        if (n < 2048)      { s0 = Wq + (size_t)k0 * 2048 + n;
                             s1 = Wq + (size_t)(k0 + 1) * 2048 + n; }
        else if (n < 2560) { s0 = Wk + (size_t)k0 * 512 + (n - 2048);
                             s1 = Wk + (size_t)(k0 + 1) * 512 + (n - 2048); }
        else               { s0 = Wv + (size_t)k0 * 512 + (n - 2560);
                             s1 = Wv + (size_t)(k0 + 1) * 512 + (n - 2560); }
        float4 a = *(const float4*)s0;
        float4 b = *(const float4*)s1;
        __half2* dst = (__half2*)(g_wqkvh + (size_t)r * 2 * NQKV + n * 2);
        dst[0] = __floats2half2_rn(a.x, b.x);
        dst[1] = __floats2half2_rn(a.y, b.y);
        dst[2] = __floats2half2_rn(a.z, b.z);
        dst[3] = __floats2half2_rn(a.w, b.w);
    }
    if (i4 < (C_ / 2) * (C_ / 4)) {
        int r = i4 / (C_ / 4);
        int n = (i4 % (C_ / 4)) * 4;
        float4 a = *(const float4*)(Wp + (size_t)(2 * r) * C_ + n);
        float4 b = *(const float4*)(Wp + (size_t)(2 * r + 1) * C_ + n);
        __half2* dst = (__half2*)(g_wph + (size_t)r * 2 * C_ + n * 2);
        dst[0] = __floats2half2_rn(a.x, b.x);
        dst[1] = __floats2half2_rn(a.y, b.y);
        dst[2] = __floats2half2_rn(a.z, b.z);
        dst[3] = __floats2half2_rn(a.w, b.w);
    }
}

// ============ fp16 cp.async 2-stage GEMM, K-slab 64, 2 CTAs/SM =============
// 128x128x64 slab, 8 warps (2x4), warp tile 64x32, m16n8k16, f32 accum.
// A fragments via ldmatrix.x4; B scalar LDS (conflict-free).
#define AW 36     // 32 data + 4 pad (half2 words per A row)
#define BW 136    // 128 data + 8 pad
#define A_WORDS (128 * AW)    // 4608
#define B_WORDS (32 * BW)     // 4352
#define STG_W (A_WORDS + B_WORDS)
#define SMEM_G (2 * STG_W * 4)   // 71680 B -> 2 CTAs/SM
#define CW 68     // V repack staging

template <int SPLIT>
__global__ void __launch_bounds__(256, 2)
gemm_hp(const __half* __restrict__ A, const __half* __restrict__ Bm,
        float* __restrict__ C0, int M, int N, int K) {
    extern __shared__ uint32_t sm[];

    const int tid  = threadIdx.x;
    const int bm   = blockIdx.y * 128;
    const int bn   = blockIdx.x * 128;
    const int warp = tid >> 5;
    const int lane = tid & 31;
    const int g    = lane >> 2;
    const int tg   = lane & 3;
    const int wm   = (warp >> 2) * 64;
    const int wn   = (warp & 3) * 32;
    const int nslab = K >> 6;

    const uint32_t sbase = smem_u32(sm);
    // per-lane ldmatrix base (words): row wm+(lane&15), col-half (lane>>4)*4
    const uint32_t lds_a = ((wm + (lane & 15)) * AW + ((lane >> 4) << 2)) * 4;

    float acc[4][4][4];
#pragma unroll
    for (int i = 0; i < 4; ++i)
#pragma unroll
        for (int j = 0; j < 4; ++j)
#pragma unroll
            for (int c = 0; c < 4; ++c) acc[i][j][c] = 0.0f;

#define ISSUE_STAGE(s, kb)                                                  \
    do {                                                                    \
        uint32_t ab = sbase + (s) * (STG_W * 4);                            \
        uint32_t bb = ab + A_WORDS * 4;                                     \
        _Pragma("unroll")                                                   \
        for (int l = 0; l < 4; ++l) {                                       \
            int id = l * 256 + tid;                                         \
            int row = id >> 3, wo = (id & 7) * 4;                           \
            cpa16(ab + (uint32_t)(row * AW + wo) * 4,                       \
                  A + (size_t)(bm + row) * K + (kb) + wo * 2);              \
        }                                                                   \
        _Pragma("unroll")                                                   \
        for (int l = 0; l < 4; ++l) {                                       \
            int id = l * 256 + tid;                                         \
            int r = id >> 5, nw = (id & 31) * 4;                            \
            cpa16(bb + (uint32_t)(r * BW + nw) * 4,                         \
                  Bm + ((size_t)((kb) >> 1) + r) * (2 * N) +                \
                      (size_t)(bn + nw) * 2);                               \
        }                                                                   \
    } while (0)

    ISSUE_STAGE(0, 0);
    cpa_commit();

    for (int i = 0; i < nslab; ++i) {
        if (i + 1 < nslab) {
            ISSUE_STAGE((i + 1) & 1, (i + 1) << 6);
            cpa_commit();
            cpa_wait<1>();
        } else {
            cpa_wait<0>();
        }
        __syncthreads();

        const uint32_t a_sm = sbase + (i & 1) * (STG_W * 4) + lds_a;
        const uint32_t* b_s = sm + (i & 1) * STG_W + A_WORDS;

#pragma unroll
        for (int ks = 0; ks < 4; ++ks) {        // four k16 chunks
            const int kp = ks * 8;
            uint32_t af[4][4], bf[4][2];
#pragma unroll
            for (int mt = 0; mt < 4; ++mt)
                ldsm4(af[mt][0], af[mt][1], af[mt][2], af[mt][3],
                      a_sm + (uint32_t)(mt * 16 * AW + kp) * 4);
#pragma unroll
            for (int nt = 0; nt < 4; ++nt) {
                int n0 = wn + nt * 8;
                bf[nt][0] = b_s[(kp + tg)     * BW + n0 + g];
                bf[nt][1] = b_s[(kp + tg + 4) * BW + n0 + g];
            }
#pragma unroll
            for (int mt = 0; mt < 4; ++mt)
#pragma unroll
                for (int nt = 0; nt < 4; ++nt)
                    mma_f16(acc[mt][nt], af[mt], bf[nt]);
        }
        __syncthreads();
    }

    if (SPLIT && bn >= 2560) {
        // ---- V tile: repack through smem into [tok/2][dk][2] fp16 ----
#pragma unroll
        for (int mt = 0; mt < 4; ++mt)
#pragma unroll
            for (int nt = 0; nt < 4; ++nt) {
                int r0 = wm + mt * 16 + g;
                int cw = (wn + nt * 8 + tg * 2) >> 1;
                sm[r0 * CW + cw]       = packh2(acc[mt][nt][0], acc[mt][nt][1]);
                sm[(r0 + 8) * CW + cw] = packh2(acc[mt][nt][2], acc[mt][nt][3]);
            }
        __syncthreads();
        uint32_t* vp32 = (uint32_t*)g_vp;
#pragma unroll
        for (int it = 0; it < 16; ++it) {
            int id = it * 256 + tid;
            int tp = id >> 6, cw = id & 63;
            uint32_t a = sm[(2 * tp) * CW + cw];
            uint32_t b = sm[(2 * tp + 1) * CW + cw];
            __half2 ah = *(__half2*)&a, bh = *(__half2*)&b;
            uint2 o;
            o.x = packh2(__low2float(ah),  __low2float(bh));
            o.y = packh2(__high2float(ah), __high2float(bh));
            *(uint2*)(vp32 + ((size_t)(bm >> 1) + tp) * 512 +
                      (bn - 2560) + 2 * cw) = o;
        }
        return;
    }

    if (SPLIT) {
        // ---- q/k tile: fused RoPE, write fp16 (q scaled for softmax) ----
        const float SCq = 0.125f * 1.4426950408889634f;
        const bool isq = (bn < 2048);
        const float scale = isq ? SCq : 1.0f;
        __half* dst = isq ? g_qh : g_kh;
        const int ldc = isq ? 2048 : 512;
        const int coff = isq ? bn : bn - 2048;
#pragma unroll
        for (int mt = 0; mt < 4; ++mt) {
#pragma unroll
            for (int nt = 0; nt < 4; ++nt) {
                int col = coff + wn + nt * 8 + tg * 2;
                int p = (col & 63) >> 1;
                int r0 = bm + wm + mt * 16 + g;
                float2 cs0 = g_rope[(r0 & (T_ - 1)) * 32 + p];
                float2 cs1 = g_rope[((r0 + 8) & (T_ - 1)) * 32 + p];
                float a0 = acc[mt][nt][0], a1 = acc[mt][nt][1];
                float a2 = acc[mt][nt][2], a3 = acc[mt][nt][3];
                *(__half2*)(dst + (size_t)r0 * ldc + col) =
                    __floats2half2_rn((a0 * cs0.x - a1 * cs0.y) * scale,
                                      (a1 * cs0.x + a0 * cs0.y) * scale);
                *(__half2*)(dst + (size_t)(r0 + 8) * ldc + col) =
                    __floats2half2_rn((a2 * cs1.x - a3 * cs1.y) * scale,
                                      (a3 * cs1.x + a2 * cs1.y) * scale);
            }
        }
        return;
    }

    // ---- plain fp32 output (out-proj) ----
#pragma unroll
    for (int mt = 0; mt < 4; ++mt) {
#pragma unroll
        for (int nt = 0; nt < 4; ++nt) {
            int r0  = bm + wm + mt * 16 + g;
            int col = bn + wn + nt * 8 + tg * 2;
            *(float2*)(C0 + (size_t)r0 * N + col) =
                make_float2(acc[mt][nt][0], acc[mt][nt][1]);
            *(float2*)(C0 + (size_t)(r0 + 8) * N + col) =
                make_float2(acc[mt][nt][2], acc[mt][nt][3]);
        }
    }
}

// ---------------- fp16 flash attention (FA2 fragment identity) -------------
// 4 CTAs/SM: regs capped at 128 via launch bounds; smem 4 x 35840B fits.
#define KW2 36
#define VW2 68
#define KSTG (64 * KW2)
#define VSTG (32 * VW2)
#define SMEM_F ((2 * KSTG + 2 * VSTG) * 4)

__global__ void __launch_bounds__(128, 4)
flash_tc(const __half* __restrict__ Q, const __half* __restrict__ K,
         const __half* __restrict__ Vp, __half* __restrict__ O) {
    extern __shared__ uint32_t fsm[];
    const uint32_t sbase = smem_u32(fsm);

    const int tid  = threadIdx.x;
    const int warp = tid >> 5;
    const int lane = tid & 31;
    const int g    = lane >> 2;
    const int tg   = lane & 3;

    const int qi = blockIdx.x;
    const int bh = blockIdx.y;
    const int b  = bh >> 5;
    const int h  = bh & 31;
    const int hk = h >> 2;
    const int q0 = qi * 64;
    const int qrow = warp * 16;
    const int bT = b * T_;

#define ISSUE_KV(j, s)                                                      \
    do {                                                                    \
        uint32_t kb = sbase + (s) * (KSTG * 4);                             \
        uint32_t vb = sbase + (2 * KSTG + (s) * VSTG) * 4;                  \
        int k0i = (j) * 64;                                                 \
        _Pragma("unroll")                                                   \
        for (int l = 0; l < 4; ++l) {                                       \
            int id = l * 128 + tid;                                         \
            int r = id >> 3, c8 = id & 7;                                   \
            cpa16(kb + (uint32_t)(r * KW2 + c8 * 4) * 4,                    \
                  K + (size_t)(bT + k0i + r) * KVDIM + hk * D_ + c8 * 8);   \
        }                                                                   \
        _Pragma("unroll")                                                   \
        for (int l = 0; l < 4; ++l) {                                       \
            int id = l * 128 + tid;                                         \
            int t2 = id >> 4, c16 = id & 15;                                \
            cpa16(vb + (uint32_t)(t2 * VW2 + c16 * 4) * 4,                  \
                  Vp + ((size_t)((bT + k0i) >> 1) + t2) * (2 * KVDIM) +     \
                      hk * 128 + c16 * 8);                                  \
        }                                                                   \
    } while (0)

    {
        uint32_t qb = sbase + KSTG * 4;
#pragma unroll
        for (int l = 0; l < 4; ++l) {
            int id = l * 128 + tid;
            int r = id >> 3, c8 = id & 7;
            cpa16(qb + (uint32_t)(r * KW2 + c8 * 4) * 4,
                  Q + (size_t)(bT + q0 + r) * C_ + h * D_ + c8 * 8);
        }
        cpa_commit();
    }
    ISSUE_KV(0, 0);
    cpa_commit();

    cpa_wait<1>();
    __syncthreads();

    uint32_t qf[4][4];
    {
        const uint32_t* Qs = fsm + KSTG;
#pragma unroll
        for (int c = 0; c < 4; ++c) {
            qf[c][0] = Qs[(qrow + g)     * KW2 + 8 * c + tg];
            qf[c][1] = Qs[(qrow + g + 8) * KW2 + 8 * c + tg];
            qf[c][2] = Qs[(qrow + g)     * KW2 + 8 * c + tg + 4];
            qf[c][3] = Qs[(qrow + g + 8) * KW2 + 8 * c + tg + 4];
        }
    }
    __syncthreads();

    if (qi >= 1) {
        ISSUE_KV(1, 1);
        cpa_commit();
    }

    float m1 = -INFINITY, m2 = -INFINITY, l1 = 0.0f, l2 = 0.0f;
    float oacc[8][4];
#pragma unroll
    for (int nt = 0; nt < 8; ++nt)
#pragma unroll
        for (int c = 0; c < 4; ++c) oacc[nt][c] = 0.0f;

    for (int j = 0; j <= qi; ++j) {
        if (j < qi) cpa_wait<1>(); else cpa_wait<0>();
        __syncthreads();

        const uint32_t* Ks = fsm + (j & 1) * KSTG;
        const uint32_t* Vs = fsm + 2 * KSTG + (j & 1) * VSTG;
        const int k0 = j * 64;

        float sacc[8][4];
#pragma unroll
        for (int nt = 0; nt < 8; ++nt)
#pragma unroll
            for (int c = 0; c < 4; ++c) sacc[nt][c] = 0.0f;

#pragma unroll
        for (int nt = 0; nt < 8; ++nt) {
#pragma unroll
            for (int c = 0; c < 4; ++c) {
                uint32_t bf[2];
                bf[0] = Ks[(nt * 8 + g) * KW2 + 8 * c + tg];
                bf[1] = Ks[(nt * 8 + g) * KW2 + 8 * c + tg + 4];
                mma_f16(sacc[nt], qf[c], bf);
            }
        }

        if (j == qi) {
            int r1 = q0 + qrow + g, r2 = r1 + 8;
#pragma unroll
            for (int nt = 0; nt < 8; ++nt) {
                int c0 = k0 + nt * 8 + tg * 2;
                if (c0     > r1) sacc[nt][0] = -INFINITY;
                if (c0 + 1 > r1) sacc[nt][1] = -INFINITY;
                if (c0     > r2) sacc[nt][2] = -INFINITY;
                if (c0 + 1 > r2) sacc[nt][3] = -INFINITY;
            }
        }

        float a1 = -INFINITY, a2 = -INFINITY;
#pragma unroll
        for (int nt = 0; nt < 8; ++nt) {
            a1 = fmaxf(a1, fmaxf(sacc[nt][0], sacc[nt][1]));
            a2 = fmaxf(a2, fmaxf(sacc[nt][2], sacc[nt][3]));
        }
        a1 = fmaxf(a1, __shfl_xor_sync(0xffffffff, a1, 1));
        a1 = fmaxf(a1, __shfl_xor_sync(0xffffffff, a1, 2));
        a2 = fmaxf(a2, __shfl_xor_sync(0xffffffff, a2, 1));
        a2 = fmaxf(a2, __shfl_xor_sync(0xffffffff, a2, 2));

        float mn1 = fmaxf(m1, a1), mn2 = fmaxf(m2, a2);
        float al1 = ex2f(m1 - mn1), al2 = ex2f(m2 - mn2);

        float s1 = 0.0f, s2 = 0.0f;
#pragma unroll
        for (int nt = 0; nt < 8; ++nt) {
            sacc[nt][0] = ex2f(sacc[nt][0] - mn1);
            sacc[nt][1] = ex2f(sacc[nt][1] - mn1);
            sacc[nt][2] = ex2f(sacc[nt][2] - mn2);
            sacc[nt][3] = ex2f(sacc[nt][3] - mn2);
            s1 += sacc[nt][0] + sacc[nt][1];
            s2 += sacc[nt][2] + sacc[nt][3];
        }
        s1 += __shfl_xor_sync(0xffffffff, s1, 1);
        s1 += __shfl_xor_sync(0xffffffff, s1, 2);
        s2 += __shfl_xor_sync(0xffffffff, s2, 1);
        s2 += __shfl_xor_sync(0xffffffff, s2, 2);

        l1 = l1 * al1 + s1;
        l2 = l2 * al2 + s2;
        m1 = mn1;
        m2 = mn2;

#pragma unroll
        for (int nt = 0; nt < 8; ++nt) {
            oacc[nt][0] *= al1; oacc[nt][1] *= al1;
            oacc[nt][2] *= al2; oacc[nt][3] *= al2;
        }

#pragma unroll
        for (int c = 0; c < 4; ++c) {
            uint32_t af[4];
            af[0] = packh2(sacc[2 * c][0],     sacc[2 * c][1]);
            af[1] = packh2(sacc[2 * c][2],     sacc[2 * c][3]);
            af[2] = packh2(sacc[2 * c + 1][0], sacc[2 * c + 1][1]);
            af[3] = packh2(sacc[2 * c + 1][2], sacc[2 * c + 1][3]);
#pragma unroll
            for (int nt = 0; nt < 8; ++nt) {
                uint32_t bf[2];
                bf[0] = Vs[(8 * c + tg)     * VW2 + nt * 8 + g];
                bf[1] = Vs[(8 * c + tg + 4) * VW2 + nt * 8 + g];
                mma_f16(oacc[nt], af, bf);
            }
        }

        __syncthreads();
        if (j + 2 <= qi) {
            ISSUE_KV(j + 2, j & 1);
            cpa_commit();
        }
    }

    float i1 = 1.0f / l1, i2 = 1.0f / l2;
    int r1 = q0 + qrow + g, r2 = r1 + 8;
#pragma unroll
    for (int nt = 0; nt < 8; ++nt) {
        int col = h * D_ + nt * 8 + tg * 2;
        __half2 lo = __floats2half2_rn(oacc[nt][0] * i1, oacc[nt][1] * i1);
        __half2 hi = __floats2half2_rn(oacc[nt][2] * i2, oacc[nt][3] * i2);
        *(__half2*)(O + (size_t)(bT + r1) * C_ + col) = lo;
        *(__half2*)(O + (size_t)(bT + r2) * C_ + col) = hi;
    }
}

// ---------------------------------------------------------------------------
extern "C" void kernel_launch(void* const* d_in, const int* in_sizes, int n_in,
                              void* d_out, int out_size) {
    const float* x  = (const float*)d_in[0];
    const float* Wq = (const float*)d_in[1];
    const float* Wk = (const float*)d_in[2];
    const float* Wv = (const float*)d_in[3];
    const float* Wp = (const float*)d_in[4];
    float* out = (float*)d_out;

    __half *qh, *kh, *vp, *xh, *wqkvh, *wph, *atth;
    cudaGetSymbolAddress((void**)&qh,    g_qh);
    cudaGetSymbolAddress((void**)&kh,    g_kh);
    cudaGetSymbolAddress((void**)&vp,    g_vp);
    cudaGetSymbolAddress((void**)&xh,    g_xh);
    cudaGetSymbolAddress((void**)&wqkvh, g_wqkvh);
    cudaGetSymbolAddress((void**)&wph,   g_wph);
    cudaGetSymbolAddress((void**)&atth,  g_atth);

    cudaFuncSetAttribute(gemm_hp<1>,
                         cudaFuncAttributeMaxDynamicSharedMemorySize, SMEM_G);
    cudaFuncSetAttribute(gemm_hp<0>,
                         cudaFuncAttributeMaxDynamicSharedMemorySize, SMEM_G);
    cudaFuncSetAttribute(flash_tc,
                         cudaFuncAttributeMaxDynamicSharedMemorySize, SMEM_F);

    // 1. fp16 pre-conversion + weight interleave + rope table
    cvt_pack<<<(M_TOK * C_ / 4 + 255) / 256, 256>>>(x, Wq, Wk, Wv, Wp);

    // 2. fused QKV projection + RoPE epilogue (q/k fp16 rotated, v packed)
    gemm_hp<1><<<dim3(NQKV / 128, M_TOK / 128), 256, SMEM_G>>>(
        xh, wqkvh, nullptr, M_TOK, NQKV, C_);

    // 3. causal flash attention with GQA (fp16 mma, 4 CTAs/SM)
    flash_tc<<<dim3(T_ / 64, B_ * H_), 128, SMEM_F>>>(qh, kh, vp, atth);

    // 4. output projection (fp16 mma)
    gemm_hp<0><<<dim3(C_ / 128, M_TOK / 128), 256, SMEM_G>>>(
        atth, wph, out, M_TOK, C_, C_);
}